// round 3
// baseline (speedup 1.0000x reference)
#include <cuda_runtime.h>
#include <math.h>

// Problem dims
#define Bn   256
#define Sn   512
#define ENCn 256
#define DECn 256
#define ATTNn 128
#define Hn   48
#define G4   1024          // 4*DEC
#define KIH  257           // 1+ENC
#define KP   272           // KIH padded up to multiple of 16

// ---------------- scratch (device globals; no allocation) ----------------
__device__ float g_encproj[(size_t)Bn * Sn * ATTNn];   // 64 MB
__device__ float g_h[Bn * DECn];
__device__ float g_c[Bn * DECn];
__device__ float g_rnnin[Bn * KP];                     // [b][0]=inp, [1..256]=context, rest 0
__device__ float g_wih[G4 * KP];                       // zero-padded copy of W_ih
__device__ float g_gp0[Bn * G4];                       // rnn_in @ W_ih^T
__device__ float g_gp1[Bn * G4];                       // h @ W_hh^T

__device__ __forceinline__ float tanh_ap(float x) {
    float y;
    asm("tanh.approx.f32 %0, %1;" : "=f"(y) : "f"(x));
    return y;
}

// ---------------- init: copy state, zero rnn_in, pad W_ih ----------------
__global__ void k_init(const float* __restrict__ h0, const float* __restrict__ c0,
                       const float* __restrict__ W_ih) {
    int i = blockIdx.x * blockDim.x + threadIdx.x;
    if (i < Bn * DECn) { g_h[i] = h0[i]; g_c[i] = c0[i]; }
    if (i < Bn * KP)   g_rnnin[i] = 0.f;
    for (long j = i; j < (long)G4 * KP; j += (long)gridDim.x * blockDim.x) {
        int r = (int)(j / KP), k = (int)(j % KP);
        g_wih[j] = (k < KIH) ? W_ih[r * KIH + k] : 0.f;
    }
}

// ---------------- K0: enc_proj = enc_outputs @ W_enc  [131072,256]x[256,128]
// BM=64, BN=128, BK=16, 256 threads, 4x8 microtile
__global__ __launch_bounds__(256) void k_encproj(const float* __restrict__ A,
                                                 const float* __restrict__ Wenc) {
    __shared__ float As[16][68];
    __shared__ float Bs[16][128];
    int m0 = blockIdx.x * 64;
    int tid = threadIdx.x;
    int tc = tid & 15, tr = tid >> 4;
    int lr = tid >> 2, lk = (tid & 3) * 4;
    int bk_r = tid >> 5;            // 0..7
    int bn_c = (tid & 31) * 4;      // 0..124
    float acc[4][8] = {};
    for (int k0 = 0; k0 < ENCn; k0 += 16) {
        float4 a4 = *(const float4*)(A + (size_t)(m0 + lr) * ENCn + k0 + lk);
        As[lk + 0][lr] = a4.x; As[lk + 1][lr] = a4.y;
        As[lk + 2][lr] = a4.z; As[lk + 3][lr] = a4.w;
        *(float4*)&Bs[bk_r][bn_c]     = *(const float4*)(Wenc + (size_t)(k0 + bk_r) * ATTNn + bn_c);
        *(float4*)&Bs[bk_r + 8][bn_c] = *(const float4*)(Wenc + (size_t)(k0 + bk_r + 8) * ATTNn + bn_c);
        __syncthreads();
#pragma unroll
        for (int kk = 0; kk < 16; kk++) {
            float4 af = *(const float4*)&As[kk][4 * tr];
            float4 b0 = *(const float4*)&Bs[kk][8 * tc];
            float4 b1 = *(const float4*)&Bs[kk][8 * tc + 4];
            float av[4] = {af.x, af.y, af.z, af.w};
            float bv[8] = {b0.x, b0.y, b0.z, b0.w, b1.x, b1.y, b1.z, b1.w};
#pragma unroll
            for (int i = 0; i < 4; i++)
#pragma unroll
                for (int j = 0; j < 8; j++) acc[i][j] += av[i] * bv[j];
        }
        __syncthreads();
    }
#pragma unroll
    for (int i = 0; i < 4; i++) {
        size_t r = (size_t)(m0 + 4 * tr + i) * ATTNn + 8 * tc;
        *(float4*)(g_encproj + r)     = make_float4(acc[i][0], acc[i][1], acc[i][2], acc[i][3]);
        *(float4*)(g_encproj + r + 4) = make_float4(acc[i][4], acc[i][5], acc[i][6], acc[i][7]);
    }
}

// ---------------- K1: attention per batch element (fused dec_proj/scores/softmax/context)
__global__ __launch_bounds__(512) void k_attn(const float* __restrict__ enc,
                                              const float* __restrict__ Wdec,
                                              const float* __restrict__ v,
                                              float* __restrict__ out, int t) {
    int b = blockIdx.x;
    int tid = threadIdx.x;
    __shared__ float sh_h[DECn];
    __shared__ float sh_dp[ATTNn];
    __shared__ float sh_v[ATTNn];
    __shared__ float sh_sc[Sn];
    __shared__ float sh_red[32];
    __shared__ float sh_ctx[ENCn];

    if (tid < DECn) sh_h[tid] = g_h[b * DECn + tid];
    if (tid >= DECn && tid < DECn + ATTNn) sh_v[tid - DECn] = v[tid - DECn];
    __syncthreads();

    // dec_proj = h[b] @ W_dec   (128 cols)
    if (tid < ATTNn) {
        float a = 0.f;
#pragma unroll 8
        for (int k = 0; k < DECn; k++) a = fmaf(sh_h[k], Wdec[k * ATTNn + tid], a);
        sh_dp[tid] = a;
    }
    __syncthreads();

    // scores: warp per s, lane owns 4 attn dims
    int w = tid >> 5, l = tid & 31;
    const float* epb = g_encproj + (size_t)b * Sn * ATTNn;
    float4 dp = *(const float4*)&sh_dp[4 * l];
    float4 vv = *(const float4*)&sh_v[4 * l];
#pragma unroll 2
    for (int s = w; s < Sn; s += 16) {
        float4 e4 = *(const float4*)(epb + (size_t)s * ATTNn + 4 * l);
        float sc = tanh_ap(e4.x + dp.x) * vv.x + tanh_ap(e4.y + dp.y) * vv.y
                 + tanh_ap(e4.z + dp.z) * vv.z + tanh_ap(e4.w + dp.w) * vv.w;
#pragma unroll
        for (int o = 16; o; o >>= 1) sc += __shfl_xor_sync(0xFFFFFFFFu, sc, o);
        if (l == 0) sh_sc[s] = sc;
    }
    __syncthreads();

    // softmax over 512 (one score per thread)
    float x = sh_sc[tid];
    float m = x;
#pragma unroll
    for (int o = 16; o; o >>= 1) m = fmaxf(m, __shfl_xor_sync(0xFFFFFFFFu, m, o));
    if (l == 0) sh_red[w] = m;
    __syncthreads();
    float bm = -INFINITY;
#pragma unroll
    for (int i = 0; i < 16; i++) bm = fmaxf(bm, sh_red[i]);
    float e = __expf(x - bm);
    float ssum = e;
#pragma unroll
    for (int o = 16; o; o >>= 1) ssum += __shfl_xor_sync(0xFFFFFFFFu, ssum, o);
    if (l == 0) sh_red[16 + w] = ssum;
    __syncthreads();
    float tot = 0.f;
#pragma unroll
    for (int i = 0; i < 16; i++) tot += sh_red[16 + i];
    float wgt = e / tot;
    sh_sc[tid] = wgt;  // each thread overwrites only its own slot
    // attn_seq output: [B,H,S] after preds block (B*H floats)
    out[(size_t)Bn * Hn + ((size_t)b * Hn + t) * Sn + tid] = wgt;
    __syncthreads();

    // context = attn_w @ enc_outputs[b]   (two threads per enc dim, split over s)
    int ed = tid & 255, half = tid >> 8;
    const float* eb = enc + (size_t)b * Sn * ENCn + ed;
    float acc = 0.f;
#pragma unroll 4
    for (int s = half; s < Sn; s += 2)
        acc = fmaf(sh_sc[s], eb[(size_t)s * ENCn], acc);
    if (half == 1) sh_ctx[ed] = acc;
    __syncthreads();
    if (half == 0) g_rnnin[b * KP + 1 + ed] = acc + sh_ctx[ed];
}

// ---------------- K2: gate partials (two NT GEMMs via blockIdx.z)
// z=0: g_gp0 = rnn_in[256,272] @ g_wih[1024,272]^T ; z=1: g_gp1 = h @ W_hh^T
// BM=64, BN=64, BK=16, 256 threads, 4x4 microtile
__global__ __launch_bounds__(256) void k_gates(const float* __restrict__ Whh) {
    int z = blockIdx.z;
    const float* Ag = z ? g_h    : g_rnnin;
    const float* Bg = z ? Whh    : g_wih;
    float*       Cg = z ? g_gp1  : g_gp0;
    int K   = z ? DECn : KP;      // lda == ldb == K in both cases

    __shared__ float As[16][68];
    __shared__ float Bs[16][68];
    int m0 = blockIdx.x * 64, n0 = blockIdx.y * 64;
    int tid = threadIdx.x;
    int tc = tid & 15, tr = tid >> 4;
    int lr = tid >> 2, lk = (tid & 3) * 4;
    float acc[4][4] = {};
    for (int k0 = 0; k0 < K; k0 += 16) {
        float4 a4 = *(const float4*)(Ag + (size_t)(m0 + lr) * K + k0 + lk);
        As[lk + 0][lr] = a4.x; As[lk + 1][lr] = a4.y;
        As[lk + 2][lr] = a4.z; As[lk + 3][lr] = a4.w;
        float4 b4 = *(const float4*)(Bg + (size_t)(n0 + lr) * K + k0 + lk);
        Bs[lk + 0][lr] = b4.x; Bs[lk + 1][lr] = b4.y;
        Bs[lk + 2][lr] = b4.z; Bs[lk + 3][lr] = b4.w;
        __syncthreads();
#pragma unroll
        for (int kk = 0; kk < 16; kk++) {
            float4 af = *(const float4*)&As[kk][4 * tr];
            float4 bf = *(const float4*)&Bs[kk][4 * tc];
            float av[4] = {af.x, af.y, af.z, af.w};
            float bv[4] = {bf.x, bf.y, bf.z, bf.w};
#pragma unroll
            for (int i = 0; i < 4; i++)
#pragma unroll
                for (int j = 0; j < 4; j++) acc[i][j] += av[i] * bv[j];
        }
        __syncthreads();
    }
#pragma unroll
    for (int i = 0; i < 4; i++) {
        size_t r = (size_t)(m0 + 4 * tr + i) * G4 + n0 + 4 * tc;
        *(float4*)(Cg + r) = make_float4(acc[i][0], acc[i][1], acc[i][2], acc[i][3]);
    }
}

// ---------------- K3: LSTM cell elementwise + output projection
__global__ __launch_bounds__(256) void k_cell(const float* __restrict__ bih,
                                              const float* __restrict__ bhh,
                                              const float* __restrict__ Wout,
                                              const float* __restrict__ bout,
                                              float* __restrict__ out, int t) {
    int b = blockIdx.x, d = threadIdx.x;
    int base = b * G4 + d;
    float gi = g_gp0[base]       + g_gp1[base]       + bih[d]       + bhh[d];
    float gf = g_gp0[base + 256] + g_gp1[base + 256] + bih[d + 256] + bhh[d + 256];
    float gg = g_gp0[base + 512] + g_gp1[base + 512] + bih[d + 512] + bhh[d + 512];
    float go = g_gp0[base + 768] + g_gp1[base + 768] + bih[d + 768] + bhh[d + 768];
    float si = 1.f / (1.f + __expf(-gi));
    float sf = 1.f / (1.f + __expf(-gf));
    float so = 1.f / (1.f + __expf(-go));
    float cn = sf * g_c[b * DECn + d] + si * tanhf(gg);   // accurate tanh in recurrence
    float hn = so * tanhf(cn);
    g_c[b * DECn + d] = cn;
    g_h[b * DECn + d] = hn;

    float p = hn * Wout[d];
    __shared__ float sred[8];
#pragma unroll
    for (int o = 16; o; o >>= 1) p += __shfl_xor_sync(0xFFFFFFFFu, p, o);
    if ((d & 31) == 0) sred[d >> 5] = p;
    __syncthreads();
    if (d == 0) {
        float s = 0.f;
#pragma unroll
        for (int i = 0; i < 8; i++) s += sred[i];
        s += bout[0];
        out[b * Hn + t] = s;          // preds [B,H]
        g_rnnin[b * KP] = s;          // inp for next step
    }
}

// ---------------- launch ----------------
extern "C" void kernel_launch(void* const* d_in, const int* in_sizes, int n_in,
                              void* d_out, int out_size) {
    (void)in_sizes; (void)n_in; (void)out_size;
    const float* enc  = (const float*)d_in[0];
    const float* h0   = (const float*)d_in[1];
    const float* c0   = (const float*)d_in[2];
    const float* Wenc = (const float*)d_in[3];
    const float* Wdec = (const float*)d_in[4];
    const float* v    = (const float*)d_in[5];
    const float* Wih  = (const float*)d_in[6];
    const float* Whh  = (const float*)d_in[7];
    const float* bih  = (const float*)d_in[8];
    const float* bhh  = (const float*)d_in[9];
    const float* Wout = (const float*)d_in[10];
    const float* bout = (const float*)d_in[11];
    float* out = (float*)d_out;

    k_init<<<272, 256>>>(h0, c0, Wih);
    k_encproj<<<(Bn * Sn) / 64, 256>>>(enc, Wenc);
    for (int t = 0; t < Hn; t++) {
        k_attn<<<Bn, 512>>>(enc, Wdec, v, out, t);
        k_gates<<<dim3(4, 16, 2), 256>>>(Whh);
        k_cell<<<Bn, 256>>>(bih, bhh, Wout, bout, out, t);
    }
}

// round 5
// speedup vs baseline: 1.5877x; 1.5877x over previous
#include <cuda_runtime.h>
#include <cuda_fp16.h>
#include <math.h>

// Problem dims
#define Bn   256
#define Sn   512
#define ENCn 256
#define DECn 256
#define ATTNn 128
#define Hn   48
#define G4   1024          // 4*DEC
#define KIH  257           // 1+ENC
#define KC   544           // 1 + 256 ctx + 256 h + 31 zero pad (34 k-tiles of 16)
#define KHALF 272          // split-K half (17 tiles)

// ---------------- scratch (device globals; no allocation) ----------------
__device__ __half g_enc16[(size_t)Bn * Sn * ENCn];   // 32 MB fp16 copy of enc_outputs
__device__ __half g_ep16[(size_t)Bn * Sn * ATTNn];   // 32 MB fp16 enc_proj
__device__ float  g_c[Bn * DECn];
__device__ float  g_cat[Bn * KC];                    // [b]: 0=inp, 1..256=context, 257..512=h, pad
__device__ float  g_wcat[G4 * KC];                   // [W_ih | W_hh] zero-padded
__device__ float  g_gp0[Bn * G4];                    // split-K partial 0
__device__ float  g_gp1[Bn * G4];                    // split-K partial 1

__device__ __forceinline__ float tanh_ap(float x) {
    float y;
    asm("tanh.approx.f32 %0, %1;" : "=f"(y) : "f"(x));
    return y;
}

// ---------------- init: state, concat weight, fp16 enc copy ----------------
__global__ void k_init(const float* __restrict__ h0, const float* __restrict__ c0,
                       const float* __restrict__ W_ih, const float* __restrict__ W_hh,
                       const float* __restrict__ enc) {
    size_t i0 = (size_t)blockIdx.x * blockDim.x + threadIdx.x;
    size_t stride = (size_t)gridDim.x * blockDim.x;
    for (size_t i = i0; i < Bn * DECn; i += stride) g_c[i] = c0[i];
    for (size_t i = i0; i < (size_t)Bn * KC; i += stride) {
        int b = (int)(i / KC), k = (int)(i % KC);
        g_cat[i] = (k >= KIH && k < KIH + DECn) ? h0[b * DECn + (k - KIH)] : 0.f;
    }
    for (size_t i = i0; i < (size_t)G4 * KC; i += stride) {
        int r = (int)(i / KC), k = (int)(i % KC);
        float w = 0.f;
        if (k < KIH) w = W_ih[r * KIH + k];
        else if (k < KIH + DECn) w = W_hh[r * DECn + (k - KIH)];
        g_wcat[i] = w;
    }
    for (size_t i = i0; i < (size_t)Bn * Sn * ENCn / 2; i += stride) {
        float2 f = *((const float2*)enc + i);
        *((__half2*)g_enc16 + i) = __floats2half2_rn(f.x, f.y);
    }
}

// ---------------- K0: enc_proj = enc_outputs @ W_enc -> fp16  [131072,256]x[256,128]
__global__ __launch_bounds__(256) void k_encproj(const float* __restrict__ A,
                                                 const float* __restrict__ Wenc) {
    __shared__ float As[16][68];
    __shared__ float Bs[16][128];
    int m0 = blockIdx.x * 64;
    int tid = threadIdx.x;
    int tc = tid & 15, tr = tid >> 4;
    int lr = tid >> 2, lk = (tid & 3) * 4;
    int bk_r = tid >> 5;
    int bn_c = (tid & 31) * 4;
    float acc[4][8] = {};
    for (int k0 = 0; k0 < ENCn; k0 += 16) {
        float4 a4 = *(const float4*)(A + (size_t)(m0 + lr) * ENCn + k0 + lk);
        As[lk + 0][lr] = a4.x; As[lk + 1][lr] = a4.y;
        As[lk + 2][lr] = a4.z; As[lk + 3][lr] = a4.w;
        *(float4*)&Bs[bk_r][bn_c]     = *(const float4*)(Wenc + (size_t)(k0 + bk_r) * ATTNn + bn_c);
        *(float4*)&Bs[bk_r + 8][bn_c] = *(const float4*)(Wenc + (size_t)(k0 + bk_r + 8) * ATTNn + bn_c);
        __syncthreads();
#pragma unroll
        for (int kk = 0; kk < 16; kk++) {
            float4 af = *(const float4*)&As[kk][4 * tr];
            float4 b0 = *(const float4*)&Bs[kk][8 * tc];
            float4 b1 = *(const float4*)&Bs[kk][8 * tc + 4];
            float av[4] = {af.x, af.y, af.z, af.w};
            float bv[8] = {b0.x, b0.y, b0.z, b0.w, b1.x, b1.y, b1.z, b1.w};
#pragma unroll
            for (int i = 0; i < 4; i++)
#pragma unroll
                for (int j = 0; j < 8; j++) acc[i][j] += av[i] * bv[j];
        }
        __syncthreads();
    }
#pragma unroll
    for (int i = 0; i < 4; i++) {
        size_t r = (size_t)(m0 + 4 * tr + i) * ATTNn + 8 * tc;
        __half2 p0 = __floats2half2_rn(acc[i][0], acc[i][1]);
        __half2 p1 = __floats2half2_rn(acc[i][2], acc[i][3]);
        __half2 p2 = __floats2half2_rn(acc[i][4], acc[i][5]);
        __half2 p3 = __floats2half2_rn(acc[i][6], acc[i][7]);
        uint4 u;
        u.x = *(unsigned*)&p0; u.y = *(unsigned*)&p1;
        u.z = *(unsigned*)&p2; u.w = *(unsigned*)&p3;
        *(uint4*)(g_ep16 + r) = u;
    }
}

// ---------------- K1: fused [cell(t-1)] + attention(t), one block per batch b
__global__ __launch_bounds__(512) void k_attn(const float* __restrict__ Wdec,
                                              const float* __restrict__ v,
                                              const float* __restrict__ bih,
                                              const float* __restrict__ bhh,
                                              const float* __restrict__ Wout,
                                              const float* __restrict__ bout,
                                              float* __restrict__ out, int t) {
    int b = blockIdx.x;
    int tid = threadIdx.x;
    __shared__ float sh_h[DECn];
    __shared__ float sh_dpp[4][ATTNn];
    __shared__ float sh_dp[ATTNn];
    __shared__ float sh_v[ATTNn];
    __shared__ float sh_sc[Sn];
    __shared__ float sh_red[32];
    __shared__ float sh_cx[3][ENCn];

    // ---- fused LSTM cell for step t-1 (consumes gates(t-1)) ----
    if (t > 0) {
        if (tid < DECn) {
            int d = tid, base = b * G4 + d;
            float gi = g_gp0[base]       + g_gp1[base]       + bih[d]       + bhh[d];
            float gf = g_gp0[base + 256] + g_gp1[base + 256] + bih[d + 256] + bhh[d + 256];
            float gg = g_gp0[base + 512] + g_gp1[base + 512] + bih[d + 512] + bhh[d + 512];
            float go = g_gp0[base + 768] + g_gp1[base + 768] + bih[d + 768] + bhh[d + 768];
            float si = 1.f / (1.f + __expf(-gi));
            float sf = 1.f / (1.f + __expf(-gf));
            float so = 1.f / (1.f + __expf(-go));
            float cn = sf * g_c[b * DECn + d] + si * tanhf(gg);
            float hn = so * tanhf(cn);
            g_c[b * DECn + d] = cn;
            sh_h[d] = hn;
            g_cat[b * KC + KIH + d] = hn;   // h part of concat input for gates(t)
            float p = hn * Wout[d];
#pragma unroll
            for (int o = 16; o; o >>= 1) p += __shfl_xor_sync(0xFFFFFFFFu, p, o);
            if ((d & 31) == 0) sh_red[d >> 5] = p;
        }
        __syncthreads();
        if (tid == 0) {
            float s = 0.f;
#pragma unroll
            for (int i = 0; i < 8; i++) s += sh_red[i];
            s += bout[0];
            out[b * Hn + (t - 1)] = s;      // preds[b][t-1]
            g_cat[b * KC] = s;              // inp for gates(t)
        }
    } else {
        if (tid < DECn) sh_h[tid] = g_cat[b * KC + KIH + tid];   // h0 (placed by init)
    }
    if (tid < ATTNn) sh_v[tid] = v[tid];
    __syncthreads();

    // ---- dec_proj = h @ W_dec  (4-way K split over thread groups) ----
    {
        int col = tid & 127, part = tid >> 7;
        float a = 0.f;
#pragma unroll 8
        for (int k = part * 64; k < part * 64 + 64; k++)
            a = fmaf(sh_h[k], Wdec[k * ATTNn + col], a);
        sh_dpp[part][col] = a;
    }
    __syncthreads();
    if (tid < ATTNn)
        sh_dp[tid] = sh_dpp[0][tid] + sh_dpp[1][tid] + sh_dpp[2][tid] + sh_dpp[3][tid];
    __syncthreads();

    // ---- scores: warp per s, lane owns 4 attn dims (fp16 enc_proj) ----
    int w = tid >> 5, l = tid & 31;
    const __half* epb = g_ep16 + (size_t)b * Sn * ATTNn;
    float4 dp = *(const float4*)&sh_dp[4 * l];
    float4 vv = *(const float4*)&sh_v[4 * l];
#pragma unroll 4
    for (int s = w; s < Sn; s += 16) {
        uint2 u = *(const uint2*)(epb + (size_t)s * ATTNn + 4 * l);
        float2 f01 = __half22float2(*(__half2*)&u.x);
        float2 f23 = __half22float2(*(__half2*)&u.y);
        float sc = tanh_ap(f01.x + dp.x) * vv.x + tanh_ap(f01.y + dp.y) * vv.y
                 + tanh_ap(f23.x + dp.z) * vv.z + tanh_ap(f23.y + dp.w) * vv.w;
#pragma unroll
        for (int o = 16; o; o >>= 1) sc += __shfl_xor_sync(0xFFFFFFFFu, sc, o);
        if (l == 0) sh_sc[s] = sc;
    }
    __syncthreads();

    // ---- softmax over 512 ----
    float x = sh_sc[tid];
    float m = x;
#pragma unroll
    for (int o = 16; o; o >>= 1) m = fmaxf(m, __shfl_xor_sync(0xFFFFFFFFu, m, o));
    if (l == 0) sh_red[w] = m;
    __syncthreads();
    float bm = -INFINITY;
#pragma unroll
    for (int i = 0; i < 16; i++) bm = fmaxf(bm, sh_red[i]);
    float e = __expf(x - bm);
    float ssum = e;
#pragma unroll
    for (int o = 16; o; o >>= 1) ssum += __shfl_xor_sync(0xFFFFFFFFu, ssum, o);
    if (l == 0) sh_red[16 + w] = ssum;
    __syncthreads();
    float tot = 0.f;
#pragma unroll
    for (int i = 0; i < 16; i++) tot += sh_red[16 + i];
    float wgt = e / tot;
    sh_sc[tid] = wgt;
    out[(size_t)Bn * Hn + ((size_t)b * Hn + t) * Sn + tid] = wgt;   // attn_seq [B,H,S]
    __syncthreads();

    // ---- context = attn_w @ enc_outputs (fp16), 2 enc dims/thread, 4-way s split ----
    {
        int j = tid & 127, part = tid >> 7;
        const __half* eb = g_enc16 + (size_t)b * Sn * ENCn + 2 * j;
        float2 acc = make_float2(0.f, 0.f);
#pragma unroll 4
        for (int s = part; s < Sn; s += 4) {
            float2 f = __half22float2(*(const __half2*)(eb + (size_t)s * ENCn));
            float ww = sh_sc[s];
            acc.x = fmaf(ww, f.x, acc.x);
            acc.y = fmaf(ww, f.y, acc.y);
        }
        if (part > 0) { sh_cx[part - 1][2 * j] = acc.x; sh_cx[part - 1][2 * j + 1] = acc.y; }
        __syncthreads();
        if (part == 0) {
            float c0v = acc.x + sh_cx[0][2 * j] + sh_cx[1][2 * j] + sh_cx[2][2 * j];
            float c1v = acc.y + sh_cx[0][2 * j + 1] + sh_cx[1][2 * j + 1] + sh_cx[2][2 * j + 1];
            g_cat[b * KC + 1 + 2 * j]     = c0v;
            g_cat[b * KC + 1 + 2 * j + 1] = c1v;
        }
    }
}

// ---------------- K2: gates = cat[256,544] @ wcat[1024,544]^T, split-K (z), double-buffered
__global__ __launch_bounds__(256) void k_gates() {
    int z = blockIdx.z;
    float* Cg = z ? g_gp1 : g_gp0;
    int kbase = z * KHALF;

    __shared__ float As[2][16][68];
    __shared__ float Bs[2][16][68];
    int m0 = blockIdx.x * 64, n0 = blockIdx.y * 64;
    int tid = threadIdx.x;
    int tc = tid & 15, tr = tid >> 4;
    int lr = tid >> 2, lk = (tid & 3) * 4;
    const float* Ap = g_cat  + (size_t)(m0 + lr) * KC + kbase + lk;
    const float* Bp = g_wcat + (size_t)(n0 + lr) * KC + kbase + lk;

    float4 pa = *(const float4*)Ap;
    float4 pb = *(const float4*)Bp;
    As[0][lk + 0][lr] = pa.x; As[0][lk + 1][lr] = pa.y;
    As[0][lk + 2][lr] = pa.z; As[0][lk + 3][lr] = pa.w;
    Bs[0][lk + 0][lr] = pb.x; Bs[0][lk + 1][lr] = pb.y;
    Bs[0][lk + 2][lr] = pb.z; Bs[0][lk + 3][lr] = pb.w;
    __syncthreads();

    float acc[4][4] = {};
    const int NT = KHALF / 16;   // 17 tiles
#pragma unroll
    for (int tt = 0; tt < NT; tt++) {
        int cur = tt & 1;
        if (tt < NT - 1) {
            pa = *(const float4*)(Ap + (tt + 1) * 16);
            pb = *(const float4*)(Bp + (tt + 1) * 16);
        }
#pragma unroll
        for (int kk = 0; kk < 16; kk++) {
            float4 af = *(const float4*)&As[cur][kk][4 * tr];
            float4 bf = *(const float4*)&Bs[cur][kk][4 * tc];
            float av[4] = {af.x, af.y, af.z, af.w};
            float bv[4] = {bf.x, bf.y, bf.z, bf.w};
#pragma unroll
            for (int i = 0; i < 4; i++)
#pragma unroll
                for (int j = 0; j < 4; j++) acc[i][j] += av[i] * bv[j];
        }
        if (tt < NT - 1) {
            int nx = cur ^ 1;
            As[nx][lk + 0][lr] = pa.x; As[nx][lk + 1][lr] = pa.y;
            As[nx][lk + 2][lr] = pa.z; As[nx][lk + 3][lr] = pa.w;
            Bs[nx][lk + 0][lr] = pb.x; Bs[nx][lk + 1][lr] = pb.y;
            Bs[nx][lk + 2][lr] = pb.z; Bs[nx][lk + 3][lr] = pb.w;
            __syncthreads();
        }
    }
#pragma unroll
    for (int i = 0; i < 4; i++) {
        size_t r = (size_t)(m0 + 4 * tr + i) * G4 + n0 + 4 * tc;
        *(float4*)(Cg + r) = make_float4(acc[i][0], acc[i][1], acc[i][2], acc[i][3]);
    }
}

// ---------------- K3: final cell for last step's preds ----------------
__global__ __launch_bounds__(256) void k_cell_final(const float* __restrict__ bih,
                                                    const float* __restrict__ bhh,
                                                    const float* __restrict__ Wout,
                                                    const float* __restrict__ bout,
                                                    float* __restrict__ out) {
    int b = blockIdx.x, d = threadIdx.x;
    int base = b * G4 + d;
    float gi = g_gp0[base]       + g_gp1[base]       + bih[d]       + bhh[d];
    float gf = g_gp0[base + 256] + g_gp1[base + 256] + bih[d + 256] + bhh[d + 256];
    float gg = g_gp0[base + 512] + g_gp1[base + 512] + bih[d + 512] + bhh[d + 512];
    float go = g_gp0[base + 768] + g_gp1[base + 768] + bih[d + 768] + bhh[d + 768];
    float si = 1.f / (1.f + __expf(-gi));
    float sf = 1.f / (1.f + __expf(-gf));
    float so = 1.f / (1.f + __expf(-go));
    float cn = sf * g_c[b * DECn + d] + si * tanhf(gg);
    float hn = so * tanhf(cn);
    float p = hn * Wout[d];
    __shared__ float sred[8];
#pragma unroll
    for (int o = 16; o; o >>= 1) p += __shfl_xor_sync(0xFFFFFFFFu, p, o);
    if ((d & 31) == 0) sred[d >> 5] = p;
    __syncthreads();
    if (d == 0) {
        float s = 0.f;
#pragma unroll
        for (int i = 0; i < 8; i++) s += sred[i];
        out[b * Hn + (Hn - 1)] = s + bout[0];
    }
}

// ---------------- launch ----------------
extern "C" void kernel_launch(void* const* d_in, const int* in_sizes, int n_in,
                              void* d_out, int out_size) {
    (void)in_sizes; (void)n_in; (void)out_size;
    const float* enc  = (const float*)d_in[0];
    const float* h0   = (const float*)d_in[1];
    const float* c0   = (const float*)d_in[2];
    const float* Wenc = (const float*)d_in[3];
    const float* Wdec = (const float*)d_in[4];
    const float* v    = (const float*)d_in[5];
    const float* Wih  = (const float*)d_in[6];
    const float* Whh  = (const float*)d_in[7];
    const float* bih  = (const float*)d_in[8];
    const float* bhh  = (const float*)d_in[9];
    const float* Wout = (const float*)d_in[10];
    const float* bout = (const float*)d_in[11];
    float* out = (float*)d_out;

    k_init<<<2048, 256>>>(h0, c0, Wih, Whh, enc);
    k_encproj<<<(Bn * Sn) / 64, 256>>>(enc, Wenc);
    for (int t = 0; t < Hn; t++) {
        k_attn<<<Bn, 512>>>(Wdec, v, bih, bhh, Wout, bout, out, t);
        k_gates<<<dim3(4, 16, 2), 256>>>();
    }
    k_cell_final<<<Bn, 256>>>(bih, bhh, Wout, bout, out);
}

// round 7
// speedup vs baseline: 1.9085x; 1.2021x over previous
#include <cuda_runtime.h>
#include <cuda_fp16.h>
#include <math.h>
#include <stdint.h>

// Problem dims
#define Bn   256
#define Sn   512
#define ENCn 256
#define DECn 256
#define ATTNn 128
#define Hn   48
#define G4   1024          // 4*DEC
#define KIH  257           // 1+ENC
#define KC   576           // 1 + 256 ctx + 256 h + 63 zero pad (36 k-tiles of 16)
#define KQ   144           // split-K quarter (9 tiles)
#define NSPLIT 4

// ---------------- scratch (device globals; no allocation) ----------------
__device__ __half g_enc16[(size_t)Bn * Sn * ENCn];   // 32 MB fp16 enc_outputs
__device__ __half g_ep16[(size_t)Bn * Sn * ATTNn];   // 32 MB fp16 enc_proj
__device__ __half g_wenc16[ENCn * ATTNn];            // fp16 W_enc [K][N]
__device__ float  g_c[Bn * DECn];
__device__ float  g_cat[Bn * KC];                    // 0=inp, 1..256=ctx, 257..512=h, pad
__device__ float  g_wcat[G4 * KC];                   // [W_ih | W_hh] zero-padded
__device__ float  g_gp[NSPLIT * Bn * G4];            // split-K partials

__device__ __forceinline__ float tanh_ap(float x) {
    float y;
    asm("tanh.approx.f32 %0, %1;" : "=f"(y) : "f"(x));
    return y;
}

// ---------------- init ----------------
__global__ void k_init(const float* __restrict__ h0, const float* __restrict__ c0,
                       const float* __restrict__ W_ih, const float* __restrict__ W_hh,
                       const float* __restrict__ enc, const float* __restrict__ Wenc) {
    size_t i0 = (size_t)blockIdx.x * blockDim.x + threadIdx.x;
    size_t stride = (size_t)gridDim.x * blockDim.x;
    for (size_t i = i0; i < Bn * DECn; i += stride) g_c[i] = c0[i];
    for (size_t i = i0; i < (size_t)Bn * KC; i += stride) {
        int b = (int)(i / KC), k = (int)(i % KC);
        g_cat[i] = (k >= KIH && k < KIH + DECn) ? h0[b * DECn + (k - KIH)] : 0.f;
    }
    for (size_t i = i0; i < (size_t)G4 * KC; i += stride) {
        int r = (int)(i / KC), k = (int)(i % KC);
        float w = 0.f;
        if (k < KIH) w = W_ih[r * KIH + k];
        else if (k < KIH + DECn) w = W_hh[r * DECn + (k - KIH)];
        g_wcat[i] = w;
    }
    for (size_t i = i0; i < (size_t)Bn * Sn * ENCn / 2; i += stride) {
        float2 f = *((const float2*)enc + i);
        *((__half2*)g_enc16 + i) = __floats2half2_rn(f.x, f.y);
    }
    for (size_t i = i0; i < (size_t)ENCn * ATTNn / 2; i += stride) {
        float2 f = *((const float2*)Wenc + i);
        *((__half2*)g_wenc16 + i) = __floats2half2_rn(f.x, f.y);
    }
}

// ---------------- K0: enc_proj via fp16 tensor cores ----------------
// C[131072,128] = enc16[131072,256] @ wenc16[256,128], block 128x128, 8 warps
__device__ __forceinline__ void ldsm_x4(uint32_t* r, const __half* p) {
    uint32_t a = (uint32_t)__cvta_generic_to_shared(p);
    asm volatile("ldmatrix.sync.aligned.m8n8.x4.shared.b16 {%0,%1,%2,%3}, [%4];"
                 : "=r"(r[0]), "=r"(r[1]), "=r"(r[2]), "=r"(r[3]) : "r"(a));
}
__device__ __forceinline__ void ldsm_x4_t(uint32_t* r, const __half* p) {
    uint32_t a = (uint32_t)__cvta_generic_to_shared(p);
    asm volatile("ldmatrix.sync.aligned.m8n8.x4.trans.shared.b16 {%0,%1,%2,%3}, [%4];"
                 : "=r"(r[0]), "=r"(r[1]), "=r"(r[2]), "=r"(r[3]) : "r"(a));
}
__device__ __forceinline__ void mma16816(float* d, const uint32_t* a, uint32_t b0, uint32_t b1) {
    asm volatile("mma.sync.aligned.m16n8k16.row.col.f32.f16.f16.f32 "
                 "{%0,%1,%2,%3}, {%4,%5,%6,%7}, {%8,%9}, {%0,%1,%2,%3};"
                 : "+f"(d[0]), "+f"(d[1]), "+f"(d[2]), "+f"(d[3])
                 : "r"(a[0]), "r"(a[1]), "r"(a[2]), "r"(a[3]), "r"(b0), "r"(b1));
}

#define LDA 72    // As row stride (halfs)
#define LDB 136   // Bs row stride (halfs)
__global__ __launch_bounds__(256) void k_encproj() {
    __shared__ __half As[128 * LDA];
    __shared__ __half Bs[64 * LDB];
    int tid = threadIdx.x;
    int wid = tid >> 5, l = tid & 31;
    int warp_m = wid & 3, warp_n = wid >> 2;       // 4 x 2 warps; warp tile 32m x 64n
    size_t m0 = (size_t)blockIdx.x * 128;

    float acc[2][8][4];
#pragma unroll
    for (int i = 0; i < 2; i++)
#pragma unroll
        for (int j = 0; j < 8; j++)
#pragma unroll
            for (int q = 0; q < 4; q++) acc[i][j][q] = 0.f;

    for (int kc = 0; kc < 4; kc++) {               // K stages of 64
#pragma unroll
        for (int it = 0; it < 4; it++) {           // A: 128x64 halfs
            int i = tid + 256 * it;
            int r = i >> 3, c = (i & 7) * 8;
            *(uint4*)&As[r * LDA + c] = *(const uint4*)&g_enc16[(m0 + r) * ENCn + kc * 64 + c];
        }
#pragma unroll
        for (int it = 0; it < 4; it++) {           // B: 64x128 halfs
            int i = tid + 256 * it;
            int r = i >> 4, c = (i & 15) * 8;
            *(uint4*)&Bs[r * LDB + c] = *(const uint4*)&g_wenc16[(size_t)(kc * 64 + r) * ATTNn + c];
        }
        __syncthreads();
#pragma unroll
        for (int ks = 0; ks < 4; ks++) {           // k-steps of 16
            uint32_t a[2][4];
#pragma unroll
            for (int mt = 0; mt < 2; mt++)
                ldsm_x4(a[mt], &As[(warp_m * 32 + mt * 16 + (l & 15)) * LDA + ks * 16 + (l >> 4) * 8]);
            uint32_t bf[4][4];
#pragma unroll
            for (int pr = 0; pr < 4; pr++)
                ldsm_x4_t(bf[pr], &Bs[(ks * 16 + (l & 15)) * LDB + warp_n * 64 + pr * 16 + (l >> 4) * 8]);
#pragma unroll
            for (int mt = 0; mt < 2; mt++)
#pragma unroll
                for (int nt = 0; nt < 8; nt++)
                    mma16816(acc[mt][nt], a[mt], bf[nt >> 1][(nt & 1) * 2], bf[nt >> 1][(nt & 1) * 2 + 1]);
        }
        __syncthreads();
    }
    // epilogue -> fp16
    int r0 = l >> 2, c0 = (l & 3) * 2;
#pragma unroll
    for (int mt = 0; mt < 2; mt++)
#pragma unroll
        for (int nt = 0; nt < 8; nt++) {
            size_t gm = m0 + warp_m * 32 + mt * 16 + r0;
            int gn = warp_n * 64 + nt * 8 + c0;
            *(__half2*)&g_ep16[gm * ATTNn + gn]       = __floats2half2_rn(acc[mt][nt][0], acc[mt][nt][1]);
            *(__half2*)&g_ep16[(gm + 8) * ATTNn + gn] = __floats2half2_rn(acc[mt][nt][2], acc[mt][nt][3]);
        }
}

// ---------------- K1: fused [cell(t-1)] + attention(t), one block per batch b
__global__ __launch_bounds__(512) void k_attn(const float* __restrict__ Wdec,
                                              const float* __restrict__ v,
                                              const float* __restrict__ bih,
                                              const float* __restrict__ bhh,
                                              const float* __restrict__ Wout,
                                              const float* __restrict__ bout,
                                              float* __restrict__ out, int t) {
    int b = blockIdx.x;
    int tid = threadIdx.x;
    __shared__ float sh_h[DECn];
    __shared__ float sh_dpp[4][ATTNn];
    __shared__ float sh_dp[ATTNn];
    __shared__ float sh_v[ATTNn];
    __shared__ float sh_sc[Sn];
    __shared__ float sh_red[32];
    __shared__ float sh_cx[3][ENCn];

    // ---- fused LSTM cell for step t-1 ----
    if (t > 0) {
        if (tid < DECn) {
            int d = tid;
            float gi = bih[d]       + bhh[d];
            float gf = bih[d + 256] + bhh[d + 256];
            float gg = bih[d + 512] + bhh[d + 512];
            float go = bih[d + 768] + bhh[d + 768];
#pragma unroll
            for (int z = 0; z < NSPLIT; z++) {
                const float* gp = g_gp + (size_t)z * Bn * G4 + b * G4 + d;
                gi += gp[0]; gf += gp[256]; gg += gp[512]; go += gp[768];
            }
            float si = 1.f / (1.f + __expf(-gi));
            float sf = 1.f / (1.f + __expf(-gf));
            float so = 1.f / (1.f + __expf(-go));
            float cn = sf * g_c[b * DECn + d] + si * tanhf(gg);
            float hn = so * tanhf(cn);
            g_c[b * DECn + d] = cn;
            sh_h[d] = hn;
            g_cat[b * KC + KIH + d] = hn;
            float p = hn * Wout[d];
#pragma unroll
            for (int o = 16; o; o >>= 1) p += __shfl_xor_sync(0xFFFFFFFFu, p, o);
            if ((d & 31) == 0) sh_red[d >> 5] = p;
        }
        __syncthreads();
        if (tid == 0) {
            float s = 0.f;
#pragma unroll
            for (int i = 0; i < 8; i++) s += sh_red[i];
            s += bout[0];
            out[b * Hn + (t - 1)] = s;
            g_cat[b * KC] = s;
        }
    } else {
        if (tid < DECn) sh_h[tid] = g_cat[b * KC + KIH + tid];
    }
    if (tid < ATTNn) sh_v[tid] = v[tid];
    __syncthreads();

    // ---- dec_proj = h @ W_dec (4-way K split) ----
    {
        int col = tid & 127, part = tid >> 7;
        float a = 0.f;
#pragma unroll 8
        for (int k = part * 64; k < part * 64 + 64; k++)
            a = fmaf(sh_h[k], Wdec[k * ATTNn + col], a);
        sh_dpp[part][col] = a;
    }
    __syncthreads();
    if (tid < ATTNn)
        sh_dp[tid] = sh_dpp[0][tid] + sh_dpp[1][tid] + sh_dpp[2][tid] + sh_dpp[3][tid];
    __syncthreads();

    // ---- scores: each warp does 4 s per pass; 8 lanes x 16 dims per s ----
    int w = tid >> 5, l = tid & 31;
    {
        int sgrp = l >> 3;            // which of 4 s in this warp-pass
        int dlo = (l & 7) * 16;       // my 16 attn dims
        float dpr[16], vr[16];
#pragma unroll
        for (int i = 0; i < 4; i++) {
            *(float4*)&dpr[4 * i] = *(float4*)&sh_dp[dlo + 4 * i];
            *(float4*)&vr[4 * i]  = *(float4*)&sh_v[dlo + 4 * i];
        }
        const __half* epb = g_ep16 + (size_t)b * Sn * ATTNn + dlo;
#pragma unroll
        for (int s0 = 0; s0 < Sn / 64; s0++) {
            int s = s0 * 64 + w * 4 + sgrp;
            const __half* row = epb + (size_t)s * ATTNn;
            uint4 u0 = *(const uint4*)row;
            uint4 u1 = *(const uint4*)(row + 8);
            float sc = 0.f;
            const __half2* h0p = (const __half2*)&u0;
            const __half2* h1p = (const __half2*)&u1;
#pragma unroll
            for (int j = 0; j < 4; j++) {
                float2 f = __half22float2(h0p[j]);
                sc = fmaf(tanh_ap(f.x + dpr[2 * j]),     vr[2 * j],     sc);
                sc = fmaf(tanh_ap(f.y + dpr[2 * j + 1]), vr[2 * j + 1], sc);
            }
#pragma unroll
            for (int j = 0; j < 4; j++) {
                float2 f = __half22float2(h1p[j]);
                sc = fmaf(tanh_ap(f.x + dpr[8 + 2 * j]),     vr[8 + 2 * j],     sc);
                sc = fmaf(tanh_ap(f.y + dpr[8 + 2 * j + 1]), vr[8 + 2 * j + 1], sc);
            }
            sc += __shfl_xor_sync(0xFFFFFFFFu, sc, 4);
            sc += __shfl_xor_sync(0xFFFFFFFFu, sc, 2);
            sc += __shfl_xor_sync(0xFFFFFFFFu, sc, 1);
            if ((l & 7) == 0) sh_sc[s] = sc;
        }
    }
    __syncthreads();

    // ---- softmax over 512 ----
    float x = sh_sc[tid];
    float m = x;
#pragma unroll
    for (int o = 16; o; o >>= 1) m = fmaxf(m, __shfl_xor_sync(0xFFFFFFFFu, m, o));
    if (l == 0) sh_red[w] = m;
    __syncthreads();
    float bm = -INFINITY;
#pragma unroll
    for (int i = 0; i < 16; i++) bm = fmaxf(bm, sh_red[i]);
    float e = __expf(x - bm);
    float ssum = e;
#pragma unroll
    for (int o = 16; o; o >>= 1) ssum += __shfl_xor_sync(0xFFFFFFFFu, ssum, o);
    if (l == 0) sh_red[16 + w] = ssum;
    __syncthreads();
    float tot = 0.f;
#pragma unroll
    for (int i = 0; i < 16; i++) tot += sh_red[16 + i];
    float wgt = e / tot;
    sh_sc[tid] = wgt;
    out[(size_t)Bn * Hn + ((size_t)b * Hn + t) * Sn + tid] = wgt;
    __syncthreads();

    // ---- context = attn_w @ enc_outputs (fp16), 2 dims/thread, 4-way s split ----
    {
        int j = tid & 127, part = tid >> 7;
        const __half* eb = g_enc16 + (size_t)b * Sn * ENCn + 2 * j;
        float2 acc = make_float2(0.f, 0.f);
#pragma unroll 8
        for (int s = part; s < Sn; s += 4) {
            float2 f = __half22float2(*(const __half2*)(eb + (size_t)s * ENCn));
            float ww = sh_sc[s];
            acc.x = fmaf(ww, f.x, acc.x);
            acc.y = fmaf(ww, f.y, acc.y);
        }
        if (part > 0) { sh_cx[part - 1][2 * j] = acc.x; sh_cx[part - 1][2 * j + 1] = acc.y; }
        __syncthreads();
        if (part == 0) {
            float c0v = acc.x + sh_cx[0][2 * j] + sh_cx[1][2 * j] + sh_cx[2][2 * j];
            float c1v = acc.y + sh_cx[0][2 * j + 1] + sh_cx[1][2 * j + 1] + sh_cx[2][2 * j + 1];
            g_cat[b * KC + 1 + 2 * j]     = c0v;
            g_cat[b * KC + 1 + 2 * j + 1] = c1v;
        }
    }
}

// ---------------- K2: gates = cat[256,576] @ wcat[1024,576]^T, split-K 4, double-buffered
__global__ __launch_bounds__(256) void k_gates() {
    int z = blockIdx.z;
    float* Cg = g_gp + (size_t)z * Bn * G4;
    int kbase = z * KQ;

    __shared__ float As[2][16][68];
    __shared__ float Bs[2][16][68];
    int m0 = blockIdx.x * 64, n0 = blockIdx.y * 64;
    int tid = threadIdx.x;
    int tc = tid & 15, tr = tid >> 4;
    int lr = tid >> 2, lk = (tid & 3) * 4;
    const float* Ap = g_cat  + (size_t)(m0 + lr) * KC + kbase + lk;
    const float* Bp = g_wcat + (size_t)(n0 + lr) * KC + kbase + lk;

    float4 pa = *(const float4*)Ap;
    float4 pb = *(const float4*)Bp;
    As[0][lk + 0][lr] = pa.x; As[0][lk + 1][lr] = pa.y;
    As[0][lk + 2][lr] = pa.z; As[0][lk + 3][lr] = pa.w;
    Bs[0][lk + 0][lr] = pb.x; Bs[0][lk + 1][lr] = pb.y;
    Bs[0][lk + 2][lr] = pb.z; Bs[0][lk + 3][lr] = pb.w;
    __syncthreads();

    float acc[4][4] = {};
    const int NT = KQ / 16;   // 9 tiles
#pragma unroll
    for (int tt = 0; tt < NT; tt++) {
        int cur = tt & 1;
        if (tt < NT - 1) {
            pa = *(const float4*)(Ap + (tt + 1) * 16);
            pb = *(const float4*)(Bp + (tt + 1) * 16);
        }
#pragma unroll
        for (int kk = 0; kk < 16; kk++) {
            float4 af = *(const float4*)&As[cur][kk][4 * tr];
            float4 bf = *(const float4*)&Bs[cur][kk][4 * tc];
            float av[4] = {af.x, af.y, af.z, af.w};
            float bv[4] = {bf.x, bf.y, bf.z, bf.w};
#pragma unroll
            for (int i = 0; i < 4; i++)
#pragma unroll
                for (int j = 0; j < 4; j++) acc[i][j] += av[i] * bv[j];
        }
        if (tt < NT - 1) {
            int nx = cur ^ 1;
            As[nx][lk + 0][lr] = pa.x; As[nx][lk + 1][lr] = pa.y;
            As[nx][lk + 2][lr] = pa.z; As[nx][lk + 3][lr] = pa.w;
            Bs[nx][lk + 0][lr] = pb.x; Bs[nx][lk + 1][lr] = pb.y;
            Bs[nx][lk + 2][lr] = pb.z; Bs[nx][lk + 3][lr] = pb.w;
            __syncthreads();
        }
    }
#pragma unroll
    for (int i = 0; i < 4; i++) {
        size_t r = (size_t)(m0 + 4 * tr + i) * G4 + n0 + 4 * tc;
        *(float4*)(Cg + r) = make_float4(acc[i][0], acc[i][1], acc[i][2], acc[i][3]);
    }
}

// ---------------- K3: final cell for last step's preds ----------------
__global__ __launch_bounds__(256) void k_cell_final(const float* __restrict__ bih,
                                                    const float* __restrict__ bhh,
                                                    const float* __restrict__ Wout,
                                                    const float* __restrict__ bout,
                                                    float* __restrict__ out) {
    int b = blockIdx.x, d = threadIdx.x;
    float gi = bih[d]       + bhh[d];
    float gf = bih[d + 256] + bhh[d + 256];
    float gg = bih[d + 512] + bhh[d + 512];
    float go = bih[d + 768] + bhh[d + 768];
#pragma unroll
    for (int z = 0; z < NSPLIT; z++) {
        const float* gp = g_gp + (size_t)z * Bn * G4 + b * G4 + d;
        gi += gp[0]; gf += gp[256]; gg += gp[512]; go += gp[768];
    }
    float si = 1.f / (1.f + __expf(-gi));
    float sf = 1.f / (1.f + __expf(-gf));
    float so = 1.f / (1.f + __expf(-go));
    float cn = sf * g_c[b * DECn + d] + si * tanhf(gg);
    float hn = so * tanhf(cn);
    float p = hn * Wout[d];
    __shared__ float sred[8];
#pragma unroll
    for (int o = 16; o; o >>= 1) p += __shfl_xor_sync(0xFFFFFFFFu, p, o);
    if ((d & 31) == 0) sred[d >> 5] = p;
    __syncthreads();
    if (d == 0) {
        float s = 0.f;
#pragma unroll
        for (int i = 0; i < 8; i++) s += sred[i];
        out[b * Hn + (Hn - 1)] = s + bout[0];
    }
}

// ---------------- launch ----------------
extern "C" void kernel_launch(void* const* d_in, const int* in_sizes, int n_in,
                              void* d_out, int out_size) {
    (void)in_sizes; (void)n_in; (void)out_size;
    const float* enc  = (const float*)d_in[0];
    const float* h0   = (const float*)d_in[1];
    const float* c0   = (const float*)d_in[2];
    const float* Wenc = (const float*)d_in[3];
    const float* Wdec = (const float*)d_in[4];
    const float* v    = (const float*)d_in[5];
    const float* Wih  = (const float*)d_in[6];
    const float* Whh  = (const float*)d_in[7];
    const float* bih  = (const float*)d_in[8];
    const float* bhh  = (const float*)d_in[9];
    const float* Wout = (const float*)d_in[10];
    const float* bout = (const float*)d_in[11];
    float* out = (float*)d_out;

    k_init<<<2048, 256>>>(h0, c0, Wih, Whh, enc, Wenc);
    k_encproj<<<(Bn * Sn) / 128, 256>>>();
    for (int t = 0; t < Hn; t++) {
        k_attn<<<Bn, 512>>>(Wdec, v, bih, bhh, Wout, bout, out, t);
        k_gates<<<dim3(4, 16, NSPLIT), 256>>>();
    }
    k_cell_final<<<Bn, 256>>>(bih, bhh, Wout, bout, out);
}

// round 10
// speedup vs baseline: 3.2872x; 1.7224x over previous
#include <cuda_runtime.h>
#include <cuda_fp16.h>
#include <math.h>
#include <stdint.h>

// Problem dims
#define Bn   256
#define Sn   512
#define ENCn 256
#define DECn 256
#define ATTNn 128
#define Hn   48
#define G4   1024          // 4*DEC
#define KIH  257           // 1+ENC
#define KC2  576           // 1 + 256 ctx + 256 h + 63 pad  (fp16 concat K)
#define KQ   144           // split-K quarter (9 k-steps of 16)
#define NSPLIT 4

// ---------------- scratch (device globals; no allocation) ----------------
__device__ __half g_enc16[(size_t)Bn * Sn * ENCn];   // fp16 enc_outputs
__device__ __half g_ep16[(size_t)Bn * Sn * ATTNn];   // fp16 enc_proj
__device__ __half g_wenc16[ENCn * ATTNn];            // fp16 W_enc [K][N]
__device__ __half g_wdec16[DECn * ATTNn];            // fp16 W_dec [K][N]
__device__ float  g_c[Bn * DECn];
__device__ __half g_cat16[Bn * KC2];                 // 0=inp, 1..256=ctx, 257..512=h, pad
__device__ __half g_wcat16[G4 * KC2];                // [W_ih | W_hh] fp16, zero-padded
__device__ float  g_gp[NSPLIT * Bn * G4];            // split-K fp32 partials

__device__ __forceinline__ float tanh_ap(float x) {
    float y;
    asm("tanh.approx.f32 %0, %1;" : "=f"(y) : "f"(x));
    return y;
}

// ---------------- mma helpers ----------------
__device__ __forceinline__ void ldsm_x4(uint32_t* r, const __half* p) {
    uint32_t a = (uint32_t)__cvta_generic_to_shared(p);
    asm volatile("ldmatrix.sync.aligned.m8n8.x4.shared.b16 {%0,%1,%2,%3}, [%4];"
                 : "=r"(r[0]), "=r"(r[1]), "=r"(r[2]), "=r"(r[3]) : "r"(a));
}
__device__ __forceinline__ void ldsm_x4_t(uint32_t* r, const __half* p) {
    uint32_t a = (uint32_t)__cvta_generic_to_shared(p);
    asm volatile("ldmatrix.sync.aligned.m8n8.x4.trans.shared.b16 {%0,%1,%2,%3}, [%4];"
                 : "=r"(r[0]), "=r"(r[1]), "=r"(r[2]), "=r"(r[3]) : "r"(a));
}
__device__ __forceinline__ void mma16816(float* d, const uint32_t* a, uint32_t b0, uint32_t b1) {
    asm volatile("mma.sync.aligned.m16n8k16.row.col.f32.f16.f16.f32 "
                 "{%0,%1,%2,%3}, {%4,%5,%6,%7}, {%8,%9}, {%0,%1,%2,%3};"
                 : "+f"(d[0]), "+f"(d[1]), "+f"(d[2]), "+f"(d[3])
                 : "r"(a[0]), "r"(a[1]), "r"(a[2]), "r"(a[3]), "r"(b0), "r"(b1));
}

// ---------------- init ----------------
__global__ void k_init(const float* __restrict__ h0, const float* __restrict__ c0,
                       const float* __restrict__ W_ih, const float* __restrict__ W_hh,
                       const float* __restrict__ enc, const float* __restrict__ Wenc,
                       const float* __restrict__ Wdec) {
    size_t i0 = (size_t)blockIdx.x * blockDim.x + threadIdx.x;
    size_t stride = (size_t)gridDim.x * blockDim.x;
    for (size_t i = i0; i < Bn * DECn; i += stride) g_c[i] = c0[i];
    for (size_t i = i0; i < (size_t)Bn * KC2; i += stride) {
        int b = (int)(i / KC2), k = (int)(i % KC2);
        float w = (k >= KIH && k < KIH + DECn) ? h0[b * DECn + (k - KIH)] : 0.f;
        g_cat16[i] = __float2half(w);
    }
    for (size_t i = i0; i < (size_t)G4 * KC2; i += stride) {
        int r = (int)(i / KC2), k = (int)(i % KC2);
        float w = 0.f;
        if (k < KIH) w = W_ih[r * KIH + k];
        else if (k < KIH + DECn) w = W_hh[r * DECn + (k - KIH)];
        g_wcat16[i] = __float2half(w);
    }
    for (size_t i = i0; i < (size_t)Bn * Sn * ENCn / 2; i += stride) {
        float2 f = *((const float2*)enc + i);
        *((__half2*)g_enc16 + i) = __floats2half2_rn(f.x, f.y);
    }
    for (size_t i = i0; i < (size_t)ENCn * ATTNn / 2; i += stride) {
        float2 f = *((const float2*)Wenc + i);
        *((__half2*)g_wenc16 + i) = __floats2half2_rn(f.x, f.y);
    }
    for (size_t i = i0; i < (size_t)DECn * ATTNn / 2; i += stride) {
        float2 f = *((const float2*)Wdec + i);
        *((__half2*)g_wdec16 + i) = __floats2half2_rn(f.x, f.y);
    }
}

// ---------------- K0: enc_proj via fp16 tensor cores ----------------
#define LDA 72    // As row stride (halfs)
#define LDB 136   // Bs row stride (halfs)
__global__ __launch_bounds__(256) void k_encproj() {
    __shared__ __half As[128 * LDA];
    __shared__ __half Bs[64 * LDB];
    int tid = threadIdx.x;
    int wid = tid >> 5, l = tid & 31;
    int warp_m = wid & 3, warp_n = wid >> 2;       // 4 x 2 warps; warp tile 32m x 64n
    size_t m0 = (size_t)blockIdx.x * 128;

    float acc[2][8][4];
#pragma unroll
    for (int i = 0; i < 2; i++)
#pragma unroll
        for (int j = 0; j < 8; j++)
#pragma unroll
            for (int q = 0; q < 4; q++) acc[i][j][q] = 0.f;

    for (int kc = 0; kc < 4; kc++) {
#pragma unroll
        for (int it = 0; it < 4; it++) {
            int i = tid + 256 * it;
            int r = i >> 3, c = (i & 7) * 8;
            *(uint4*)&As[r * LDA + c] = *(const uint4*)&g_enc16[(m0 + r) * ENCn + kc * 64 + c];
        }
#pragma unroll
        for (int it = 0; it < 4; it++) {
            int i = tid + 256 * it;
            int r = i >> 4, c = (i & 15) * 8;
            *(uint4*)&Bs[r * LDB + c] = *(const uint4*)&g_wenc16[(size_t)(kc * 64 + r) * ATTNn + c];
        }
        __syncthreads();
#pragma unroll
        for (int ks = 0; ks < 4; ks++) {
            uint32_t a[2][4];
#pragma unroll
            for (int mt = 0; mt < 2; mt++)
                ldsm_x4(a[mt], &As[(warp_m * 32 + mt * 16 + (l & 15)) * LDA + ks * 16 + (l >> 4) * 8]);
            uint32_t bf[4][4];
#pragma unroll
            for (int pr = 0; pr < 4; pr++)
                ldsm_x4_t(bf[pr], &Bs[(ks * 16 + (l & 15)) * LDB + warp_n * 64 + pr * 16 + (l >> 4) * 8]);
#pragma unroll
            for (int mt = 0; mt < 2; mt++)
#pragma unroll
                for (int nt = 0; nt < 8; nt++)
                    mma16816(acc[mt][nt], a[mt], bf[nt >> 1][(nt & 1) * 2], bf[nt >> 1][(nt & 1) * 2 + 1]);
        }
        __syncthreads();
    }
    int r0 = l >> 2, c0 = (l & 3) * 2;
#pragma unroll
    for (int mt = 0; mt < 2; mt++)
#pragma unroll
        for (int nt = 0; nt < 8; nt++) {
            size_t gm = m0 + warp_m * 32 + mt * 16 + r0;
            int gn = warp_n * 64 + nt * 8 + c0;
            *(__half2*)&g_ep16[gm * ATTNn + gn]       = __floats2half2_rn(acc[mt][nt][0], acc[mt][nt][1]);
            *(__half2*)&g_ep16[(gm + 8) * ATTNn + gn] = __floats2half2_rn(acc[mt][nt][2], acc[mt][nt][3]);
        }
}

// ---------------- K1: fused [cell(t-1)] + attention(t), one block per batch b
__global__ __launch_bounds__(512, 2) void k_attn(const float* __restrict__ v,
                                                 const float* __restrict__ bih,
                                                 const float* __restrict__ bhh,
                                                 const float* __restrict__ Wout,
                                                 const float* __restrict__ bout,
                                                 float* __restrict__ out, int t) {
    int b = blockIdx.x;
    int tid = threadIdx.x;
    __shared__ float sh_h[DECn];
    __shared__ float sh_dpp[8][ATTNn];
    __shared__ float sh_dp[ATTNn];
    __shared__ float sh_v[ATTNn];
    __shared__ float sh_sc[Sn];
    __shared__ float sh_red[32];
    __shared__ float sh_cx[3][ENCn];

    // ---- fused LSTM cell for step t-1 ----
    if (t > 0) {
        if (tid < DECn) {
            int d = tid;
            float gi = bih[d]       + bhh[d];
            float gf = bih[d + 256] + bhh[d + 256];
            float gg = bih[d + 512] + bhh[d + 512];
            float go = bih[d + 768] + bhh[d + 768];
#pragma unroll
            for (int z = 0; z < NSPLIT; z++) {
                const float* gp = g_gp + (size_t)z * Bn * G4 + b * G4 + d;
                gi += gp[0]; gf += gp[256]; gg += gp[512]; go += gp[768];
            }
            float si = 1.f / (1.f + __expf(-gi));
            float sf = 1.f / (1.f + __expf(-gf));
            float so = 1.f / (1.f + __expf(-go));
            float cn = sf * g_c[b * DECn + d] + si * tanhf(gg);
            float hn = so * tanhf(cn);
            g_c[b * DECn + d] = cn;
            sh_h[d] = hn;
            g_cat16[b * KC2 + KIH + d] = __float2half(hn);
            float p = hn * Wout[d];
#pragma unroll
            for (int o = 16; o; o >>= 1) p += __shfl_xor_sync(0xFFFFFFFFu, p, o);
            if ((d & 31) == 0) sh_red[d >> 5] = p;
        }
        __syncthreads();
        if (tid == 0) {
            float s = 0.f;
#pragma unroll
            for (int i = 0; i < 8; i++) s += sh_red[i];
            s += bout[0];
            out[b * Hn + (t - 1)] = s;
            g_cat16[b * KC2] = __float2half(s);
        }
    } else {
        if (tid < DECn) sh_h[tid] = __half2float(g_cat16[b * KC2 + KIH + tid]);
    }
    if (tid < ATTNn) sh_v[tid] = v[tid];
    __syncthreads();

    // ---- dec_proj = h @ W_dec (fp16 weights, 8-way K split, 2 cols/thread) ----
    {
        int c2 = (tid & 63) * 2, part = tid >> 6;       // part 0..7, 32 k each
        float2 a = make_float2(0.f, 0.f);
#pragma unroll 8
        for (int k = part * 32; k < part * 32 + 32; k++) {
            float2 w = __half22float2(*(const __half2*)&g_wdec16[k * ATTNn + c2]);
            float hk = sh_h[k];
            a.x = fmaf(hk, w.x, a.x);
            a.y = fmaf(hk, w.y, a.y);
        }
        sh_dpp[part][c2] = a.x; sh_dpp[part][c2 + 1] = a.y;
    }
    __syncthreads();
    if (tid < ATTNn) {
        float s = 0.f;
#pragma unroll
        for (int i = 0; i < 8; i++) s += sh_dpp[i][tid];
        sh_dp[tid] = s;
    }
    __syncthreads();

    // ---- scores: warp handles 2 s per pass; 16 lanes x 8 dims each ----
    int w = tid >> 5, l = tid & 31;
    {
        int sgrp = l >> 4;            // which of 2 s in this pass
        int dlo = (l & 15) * 8;       // my 8 attn dims
        float dpr[8], vr[8];
        *(float4*)&dpr[0] = *(float4*)&sh_dp[dlo];
        *(float4*)&dpr[4] = *(float4*)&sh_dp[dlo + 4];
        *(float4*)&vr[0]  = *(float4*)&sh_v[dlo];
        *(float4*)&vr[4]  = *(float4*)&sh_v[dlo + 4];
        const __half* epb = g_ep16 + (size_t)b * Sn * ATTNn + dlo;
#pragma unroll
        for (int p = 0; p < 16; p++) {
            int s = p * 32 + w * 2 + sgrp;
            uint4 u = *(const uint4*)(epb + (size_t)s * ATTNn);
            const __half2* hp = (const __half2*)&u;
            float sc = 0.f;
#pragma unroll
            for (int j = 0; j < 4; j++) {
                float2 f = __half22float2(hp[j]);
                sc = fmaf(tanh_ap(f.x + dpr[2 * j]),     vr[2 * j],     sc);
                sc = fmaf(tanh_ap(f.y + dpr[2 * j + 1]), vr[2 * j + 1], sc);
            }
            sc += __shfl_xor_sync(0xFFFFFFFFu, sc, 8);
            sc += __shfl_xor_sync(0xFFFFFFFFu, sc, 4);
            sc += __shfl_xor_sync(0xFFFFFFFFu, sc, 2);
            sc += __shfl_xor_sync(0xFFFFFFFFu, sc, 1);
            if ((l & 15) == 0) sh_sc[s] = sc;
        }
    }
    __syncthreads();

    // ---- softmax over 512 (scores bounded by sum|v| ~ 5; no max pass needed) ----
    float e = __expf(sh_sc[tid]);
    float ssum = e;
#pragma unroll
    for (int o = 16; o; o >>= 1) ssum += __shfl_xor_sync(0xFFFFFFFFu, ssum, o);
    if (l == 0) sh_red[w] = ssum;
    __syncthreads();
    float tot = 0.f;
#pragma unroll
    for (int i = 0; i < 16; i++) tot += sh_red[i];
    float wgt = e / tot;
    sh_sc[tid] = wgt;
    out[(size_t)Bn * Hn + ((size_t)b * Hn + t) * Sn + tid] = wgt;
    __syncthreads();

    // ---- context = attn_w @ enc_outputs (fp16), 2 dims/thread, 4-way s split ----
    {
        int j = tid & 127, part = tid >> 7;
        const __half* eb = g_enc16 + (size_t)b * Sn * ENCn + 2 * j;
        float2 acc = make_float2(0.f, 0.f);
#pragma unroll 8
        for (int s = part; s < Sn; s += 4) {
            float2 f = __half22float2(*(const __half2*)(eb + (size_t)s * ENCn));
            float ww = sh_sc[s];
            acc.x = fmaf(ww, f.x, acc.x);
            acc.y = fmaf(ww, f.y, acc.y);
        }
        if (part > 0) { sh_cx[part - 1][2 * j] = acc.x; sh_cx[part - 1][2 * j + 1] = acc.y; }
        __syncthreads();
        if (part == 0) {
            float c0v = acc.x + sh_cx[0][2 * j] + sh_cx[1][2 * j] + sh_cx[2][2 * j];
            float c1v = acc.y + sh_cx[0][2 * j + 1] + sh_cx[1][2 * j + 1] + sh_cx[2][2 * j + 1];
            // scalar __half stores: destination half-index is odd (1+2j) -> a
            // vector half2 store here is misaligned (byte offset 2+4j). R8 bug.
            g_cat16[b * KC2 + 1 + 2 * j]     = __float2half(c0v);
            g_cat16[b * KC2 + 1 + 2 * j + 1] = __float2half(c1v);
        }
    }
}

// ---------------- K2: gates via fp16 tensor cores, NT, split-K 4 ----------------
// C_z[256,1024] += cat16[256, z*144 : +144] @ wcat16[1024, same]^T
#define LDG16 24   // smem row stride in halfs (48B, 16B-aligned)
__global__ __launch_bounds__(256) void k_gates16() {
    int z = blockIdx.z;
    float* Cg = g_gp + (size_t)z * Bn * G4;
    int kbase = z * KQ;

    __shared__ __half As[2][64 * LDG16];    // 64 x 16 per stage
    __shared__ __half Bs[2][128 * LDG16];   // 128 x 16 per stage
    int m0 = blockIdx.x * 64, n0 = blockIdx.y * 128;
    int tid = threadIdx.x;
    int wid = tid >> 5, l = tid & 31;
    int warp_m = wid & 1, warp_n = wid >> 1;    // 2m x 4n warps; warp tile 32m x 32n

    // stage-load indices
    int ar = tid >> 2, ac = (tid & 3) * 4;      // A: 64 rows x 16, uint2 (4 halfs)
    int br = tid >> 1, bc = (tid & 1) * 8;      // B: 128 rows x 16, uint4 (8 halfs)
    const __half* Ap = g_cat16  + (size_t)(m0 + ar) * KC2 + kbase + ac;
    const __half* Bp = g_wcat16 + (size_t)(n0 + br) * KC2 + kbase + bc;

    uint2 pa = *(const uint2*)Ap;
    uint4 pb = *(const uint4*)Bp;
    *(uint2*)&As[0][ar * LDG16 + ac] = pa;
    *(uint4*)&Bs[0][br * LDG16 + bc] = pb;
    __syncthreads();

    float acc[2][4][4];
#pragma unroll
    for (int i = 0; i < 2; i++)
#pragma unroll
        for (int j = 0; j < 4; j++)
#pragma unroll
            for (int q = 0; q < 4; q++) acc[i][j][q] = 0.f;

    const int NT = KQ / 16;   // 9 stages
#pragma unroll
    for (int tt = 0; tt < NT; tt++) {
        int cur = tt & 1;
        if (tt < NT - 1) {
            pa = *(const uint2*)(Ap + (tt + 1) * 16);
            pb = *(const uint4*)(Bp + (tt + 1) * 16);
        }
        uint32_t a[2][4];
#pragma unroll
        for (int mt = 0; mt < 2; mt++)
            ldsm_x4(a[mt], &As[cur][(warp_m * 32 + mt * 16 + (l & 15)) * LDG16 + (l >> 4) * 8]);
        uint32_t bq[2][4];
#pragma unroll
        for (int bt = 0; bt < 2; bt++)
            ldsm_x4(bq[bt], &Bs[cur][(warp_n * 32 + bt * 16 + (l & 15)) * LDG16 + (l >> 4) * 8]);
#pragma unroll
        for (int mt = 0; mt < 2; mt++)
#pragma unroll
            for (int bt = 0; bt < 2; bt++) {
                mma16816(acc[mt][bt * 2 + 0], a[mt], bq[bt][0], bq[bt][2]);   // n 0-7
                mma16816(acc[mt][bt * 2 + 1], a[mt], bq[bt][1], bq[bt][3]);   // n 8-15
            }
        if (tt < NT - 1) {
            int nx = cur ^ 1;
            *(uint2*)&As[nx][ar * LDG16 + ac] = pa;
            *(uint4*)&Bs[nx][br * LDG16 + bc] = pb;
            __syncthreads();
        }
    }

    int r0 = l >> 2, c0 = (l & 3) * 2;
#pragma unroll
    for (int mt = 0; mt < 2; mt++)
#pragma unroll
        for (int nt = 0; nt < 4; nt++) {
            int gm = m0 + warp_m * 32 + mt * 16 + r0;
            int gn = n0 + warp_n * 32 + (nt >> 1) * 16 + (nt & 1) * 8 + c0;
            *(float2*)&Cg[(size_t)gm * G4 + gn]       = make_float2(acc[mt][nt][0], acc[mt][nt][1]);
            *(float2*)&Cg[(size_t)(gm + 8) * G4 + gn] = make_float2(acc[mt][nt][2], acc[mt][nt][3]);
        }
}

// ---------------- K3: final cell for last step's preds ----------------
__global__ __launch_bounds__(256) void k_cell_final(const float* __restrict__ bih,
                                                    const float* __restrict__ bhh,
                                                    const float* __restrict__ Wout,
                                                    const float* __restrict__ bout,
                                                    float* __restrict__ out) {
    int b = blockIdx.x, d = threadIdx.x;
    float gi = bih[d]       + bhh[d];
    float gf = bih[d + 256] + bhh[d + 256];
    float gg = bih[d + 512] + bhh[d + 512];
    float go = bih[d + 768] + bhh[d + 768];
#pragma unroll
    for (int z = 0; z < NSPLIT; z++) {
        const float* gp = g_gp + (size_t)z * Bn * G4 + b * G4 + d;
        gi += gp[0]; gf += gp[256]; gg += gp[512]; go += gp[768];
    }
    float si = 1.f / (1.f + __expf(-gi));
    float sf = 1.f / (1.f + __expf(-gf));
    float so = 1.f / (1.f + __expf(-go));
    float cn = sf * g_c[b * DECn + d] + si * tanhf(gg);
    float hn = so * tanhf(cn);
    float p = hn * Wout[d];
    __shared__ float sred[8];
#pragma unroll
    for (int o = 16; o; o >>= 1) p += __shfl_xor_sync(0xFFFFFFFFu, p, o);
    if ((d & 31) == 0) sred[d >> 5] = p;
    __syncthreads();
    if (d == 0) {
        float s = 0.f;
#pragma unroll
        for (int i = 0; i < 8; i++) s += sred[i];
        out[b * Hn + (Hn - 1)] = s + bout[0];
    }
}

// ---------------- launch ----------------
extern "C" void kernel_launch(void* const* d_in, const int* in_sizes, int n_in,
                              void* d_out, int out_size) {
    (void)in_sizes; (void)n_in; (void)out_size;
    const float* enc  = (const float*)d_in[0];
    const float* h0   = (const float*)d_in[1];
    const float* c0   = (const float*)d_in[2];
    const float* Wenc = (const float*)d_in[3];
    const float* Wdec = (const float*)d_in[4];
    const float* v    = (const float*)d_in[5];
    const float* Wih  = (const float*)d_in[6];
    const float* Whh  = (const float*)d_in[7];
    const float* bih  = (const float*)d_in[8];
    const float* bhh  = (const float*)d_in[9];
    const float* Wout = (const float*)d_in[10];
    const float* bout = (const float*)d_in[11];
    float* out = (float*)d_out;

    k_init<<<2048, 256>>>(h0, c0, Wih, Whh, enc, Wenc, Wdec);
    k_encproj<<<(Bn * Sn) / 128, 256>>>();
    for (int t = 0; t < Hn; t++) {
        k_attn<<<Bn, 512>>>(v, bih, bhh, Wout, bout, out, t);
        k_gates16<<<dim3(4, 8, NSPLIT), 256>>>();
    }
    k_cell_final<<<Bn, 256>>>(bih, bhh, Wout, bout, out);
}